// round 14
// baseline (speedup 1.0000x reference)
#include <cuda_runtime.h>
#include <cuda_fp16.h>
#include <math.h>

// ---------------- dims ----------------
#define BB    8
#define NNODE 1024
#define DD    256
#define HH    8
#define DHH   32
#define DFFX  1024
#define LGN   2
#define LTN   2
#define NBCAP 256
#define MTOT  (BB*NNODE)
#define SPLK  4

// ---------------- scratch (device globals; no runtime allocation) ----------------
__device__ float                 g_XC[MTOT*DD];
__device__ __align__(16) __half  g_XCH[MTOT*DD];
__device__ __align__(16) __half  g_EMBH[MTOT*DD];
__device__ __align__(16) __half  g_HBH[MTOT*HH*DD];
__device__ float                 g_AS[MTOT*HH];
__device__ float                 g_AD[MTOT*HH];
__device__ float                 g_ASP[32*MTOT];
__device__ float                 g_ADP[32*MTOT];
__device__ __align__(16) __half  g_QKVH[MTOT*3*DD];
__device__ __align__(16) __half  g_WQKVH[LTN*DD*3*DD];
__device__ float                 g_BQKV[LTN*3*DD];
__device__ __align__(16) __half  g_GATWH[LGN*HH*DD*DD];
__device__ __align__(16) __half  g_WOH[LTN*DD*DD];
__device__ __align__(16) __half  g_W1H[LTN*DD*DFFX];
__device__ __align__(16) __half  g_W2H[LTN*DFFX*DD];
__device__ __align__(16) __half  g_AOH[MTOT*DD];
__device__ float                 g_Y [MTOT*DD];
__device__ __align__(16) __half  g_YH[MTOT*DD];
__device__ __align__(16) __half  g_FFH[MTOT*DFFX];
__device__ float                 g_PART[SPLK*MTOT*DD];
__device__ unsigned              g_BITS[MTOT*(NNODE/32)];
__device__ int                   g_NBR[MTOT*NBCAP];
__device__ int                   g_CNT[MTOT];

// ---------------- helpers ----------------
__device__ __forceinline__ void mma_f16(float* c, const unsigned* a, const unsigned* b) {
    asm volatile(
        "mma.sync.aligned.m16n8k16.row.col.f32.f16.f16.f32 "
        "{%0,%1,%2,%3}, {%4,%5,%6,%7}, {%8,%9}, {%0,%1,%2,%3};\n"
        : "+f"(c[0]), "+f"(c[1]), "+f"(c[2]), "+f"(c[3])
        : "r"(a[0]), "r"(a[1]), "r"(a[2]), "r"(a[3]), "r"(b[0]), "r"(b[1]));
}

__device__ __forceinline__ unsigned saddr(const void* p) {
    return (unsigned)__cvta_generic_to_shared(p);
}
__device__ __forceinline__ void cp16(unsigned dst, const void* src) {
    asm volatile("cp.async.cg.shared.global [%0], [%1], 16;\n" :: "r"(dst), "l"(src));
}
__device__ __forceinline__ void cp_commit() {
    asm volatile("cp.async.commit_group;\n" ::: "memory");
}
template<int N>
__device__ __forceinline__ void cp_wait() {
    asm volatile("cp.async.wait_group %0;\n" :: "n"(N) : "memory");
}
__device__ __forceinline__ void ldsm4(unsigned& r0, unsigned& r1, unsigned& r2, unsigned& r3,
                                      unsigned addr) {
    asm volatile("ldmatrix.sync.aligned.m8n8.x4.shared.b16 {%0,%1,%2,%3}, [%4];"
                 : "=r"(r0), "=r"(r1), "=r"(r2), "=r"(r3) : "r"(addr));
}
__device__ __forceinline__ void ldsm4t(unsigned& r0, unsigned& r1, unsigned& r2, unsigned& r3,
                                       unsigned addr) {
    asm volatile("ldmatrix.sync.aligned.m8n8.x4.trans.shared.b16 {%0,%1,%2,%3}, [%4];"
                 : "=r"(r0), "=r"(r1), "=r"(r2), "=r"(r3) : "r"(addr));
}

// ---------------- adjacency pack ----------------
__global__ void pack_adj_k(const int* __restrict__ mask, unsigned* __restrict__ bits) {
    int idx = blockIdx.x * blockDim.x + threadIdx.x;
    int t  = idx & (NNODE - 1);
    int sw = (idx >> 10) & 31;
    int b  = idx >> 15;
    const int* mp = mask + ((size_t)b * NNODE + (size_t)sw * 32) * NNODE + t;
    unsigned w = 0;
    #pragma unroll
    for (int i = 0; i < 32; i++)
        if (mp[(size_t)i * NNODE] > 0) w |= (1u << i);
    int s0 = sw * 32;
    if (t >= s0 && t < s0 + 32) w |= (1u << (t - s0));
    bits[(b * NNODE + t) * 32 + sw] = w;
}

// ---------------- neighbor list build ----------------
__global__ void build_nbr_k(const unsigned* __restrict__ bits,
                            int* __restrict__ nbr, int* __restrict__ cnt) {
    int bt = blockIdx.x * blockDim.x + threadIdx.x;
    if (bt >= MTOT) return;
    const unsigned* bw = bits + (size_t)bt * 32;
    int* np = nbr + (size_t)bt * NBCAP;
    int c = 0;
    #pragma unroll 4
    for (int w = 0; w < 32; w++) {
        unsigned m = bw[w];
        while (m) {
            int bit = __ffs(m) - 1;
            m &= m - 1;
            if (c < NBCAP) np[c] = w * 32 + bit;
            c++;
        }
    }
    cnt[bt] = c < NBCAP ? c : NBCAP;
}

// ---------------- fused fp32 -> fp16 convert of all weights + emb ----------------
#define CV_N1 (MTOT*DD)
#define CV_N2 (LGN*HH*DD*DD)
#define CV_N3 (LTN*DD*DD)
#define CV_N4 (LTN*DD*DFFX)
#define CV_N5 (LTN*DFFX*DD)
#define CV_TOT (CV_N1+CV_N2+CV_N3+CV_N4+CV_N5)

__global__ void cvt_all_k(const float* __restrict__ emb, const float* __restrict__ gatW,
                          const float* __restrict__ Wo, const float* __restrict__ W1,
                          const float* __restrict__ W2)
{
    int i = (blockIdx.x * 256 + threadIdx.x) * 4;
    if (i >= CV_TOT) return;
    const float* src; __half* dst; int off;
    if (i < CV_N1)                         { src = emb;  dst = g_EMBH;  off = i; }
    else if (i < CV_N1 + CV_N2)            { src = gatW; dst = g_GATWH; off = i - CV_N1; }
    else if (i < CV_N1 + CV_N2 + CV_N3)    { src = Wo;   dst = g_WOH;   off = i - CV_N1 - CV_N2; }
    else if (i < CV_N1 + CV_N2 + CV_N3 + CV_N4)
                                           { src = W1;   dst = g_W1H;   off = i - CV_N1 - CV_N2 - CV_N3; }
    else                                   { src = W2;   dst = g_W2H;   off = i - CV_N1 - CV_N2 - CV_N3 - CV_N4; }
    float4 v = *(const float4*)(src + off);
    *(__half2*)(dst + off)     = __floats2half2_rn(v.x, v.y);
    *(__half2*)(dst + off + 2) = __floats2half2_rn(v.z, v.w);
}

// ---------------- QKV pack ----------------
__global__ void pack_qkv_k(const float* __restrict__ Wq, const float* __restrict__ Wk,
                           const float* __restrict__ Wv, const float* __restrict__ bq,
                           const float* __restrict__ bk, const float* __restrict__ bv,
                           __half* __restrict__ W, float* __restrict__ Bb)
{
    int idx = blockIdx.x * 256 + threadIdx.x;
    if (idx >= LTN * DD * 3 * DD) return;
    int n = idx % (3 * DD);
    int k = (idx / (3 * DD)) % DD;
    int l = idx / (3 * DD * DD);
    float v;
    if (n < DD)            v = Wq[((size_t)l * DD + k) * DD + n];
    else if (n < 2 * DD)   v = Wk[((size_t)l * DD + k) * DD + n - DD];
    else                   v = Wv[((size_t)l * DD + k) * DD + n - 2 * DD];
    W[idx] = __float2half_rn(v);
    if (k == 0) {
        float bvv;
        if (n < DD)          bvv = bq[l * DD + n];
        else if (n < 2 * DD) bvv = bk[l * DD + n - DD];
        else                 bvv = bv[l * DD + n - 2 * DD];
        Bb[l * 3 * DD + n] = bvv;
    }
}

// ---------------- fp16 tensor-core GEMM: 2-stage cp.async + ldmatrix ----------------
template<bool BT, int ACT, int HALF_OUT, int ASAD, int SPLITZ>
__global__ void __launch_bounds__(256) hgemm_k(
    int M, int Ncol, int K,
    const __half* __restrict__ A, int lda,
    const __half* __restrict__ B, int ldb,
    void* __restrict__ Cv, int ldc,
    const float* __restrict__ bias,
    const float* __restrict__ attS, const float* __restrict__ attD,
    float* __restrict__ ASP, float* __restrict__ ADP)
{
    if (SPLITZ > 1) {
        int Kc = K / SPLITZ;
        A += (size_t)blockIdx.z * Kc;
        B += (size_t)blockIdx.z * Kc * ldb;
        Cv = (void*)((float*)Cv + (size_t)blockIdx.z * M * Ncol);
        K = Kc;
    }
    __shared__ __align__(16) __half sA[2][128 * 24];
    __shared__ __align__(16) __half sB[2][3072];
    const int tid  = threadIdx.x;
    const int lane = tid & 31, wid = tid >> 5;
    const int wm = wid & 3, wn = wid >> 2;
    const int m0 = blockIdx.y * 128, n0 = blockIdx.x * 128;
    const int r = lane >> 2, cq = lane & 3;

    float acc[2][8][4];
    #pragma unroll
    for (int mt = 0; mt < 2; mt++)
        #pragma unroll
        for (int nt = 0; nt < 8; nt++)
            #pragma unroll
            for (int u = 0; u < 4; u++) acc[mt][nt][u] = 0.f;

    const int T = K / 16;

    auto loadT = [&](int st, int k0) {
        {
            int m = tid >> 1, c = tid & 1;
            cp16(saddr(&sA[st][m * 24 + c * 8]), A + (size_t)(m0 + m) * lda + k0 + c * 8);
        }
        if (BT) {
            int n = tid >> 1, c = tid & 1;
            cp16(saddr(&sB[st][n * 24 + c * 8]), B + (size_t)(n0 + n) * ldb + k0 + c * 8);
        } else {
            int kk = tid >> 4, c = tid & 15;
            cp16(saddr(&sB[st][kk * 136 + c * 8]), B + (size_t)(k0 + kk) * ldb + n0 + c * 8);
        }
        cp_commit();
    };

    loadT(0, 0);
    for (int t = 0; t < T; t++) {
        if (t + 1 < T) { loadT((t + 1) & 1, (t + 1) * 16); cp_wait<1>(); }
        else           { cp_wait<0>(); }
        __syncthreads();
        const int st = t & 1;

        unsigned af[2][4], bf[8][2];
        #pragma unroll
        for (int mt = 0; mt < 2; mt++) {
            int mrow = wm * 32 + mt * 16;
            unsigned addr = saddr(&sA[st][(mrow + (lane & 15)) * 24 + (lane >> 4) * 8]);
            ldsm4(af[mt][0], af[mt][1], af[mt][2], af[mt][3], addr);
        }
        #pragma unroll
        for (int p = 0; p < 4; p++) {
            int nb = wn * 64 + p * 16;
            if (BT) {
                int row = nb + (lane & 7) + ((lane >> 4) << 3);
                int col = ((lane >> 3) & 1) * 8;
                unsigned addr = saddr(&sB[st][row * 24 + col]);
                ldsm4(bf[2 * p][0], bf[2 * p][1], bf[2 * p + 1][0], bf[2 * p + 1][1], addr);
            } else {
                int krow = (lane & 7) + (((lane >> 3) & 1) << 3);
                int coln = nb + (lane >> 4) * 8;
                unsigned addr = saddr(&sB[st][krow * 136 + coln]);
                ldsm4t(bf[2 * p][0], bf[2 * p][1], bf[2 * p + 1][0], bf[2 * p + 1][1], addr);
            }
        }
        #pragma unroll
        for (int mt = 0; mt < 2; mt++)
            #pragma unroll
            for (int nt = 0; nt < 8; nt++)
                mma_f16(acc[mt][nt], af[mt], bf[nt]);
        __syncthreads();
    }

    if (ASAD) {
        float sS[2][2] = {{0,0},{0,0}}, sD[2][2] = {{0,0},{0,0}};
        #pragma unroll
        for (int mt = 0; mt < 2; mt++)
            #pragma unroll
            for (int nt = 0; nt < 8; nt++)
                #pragma unroll
                for (int u = 0; u < 4; u++) {
                    int g = n0 + wn * 64 + nt * 8 + cq * 2 + (u & 1);
                    float v = acc[mt][nt][u];
                    sS[mt][u >> 1] += v * attS[g];
                    sD[mt][u >> 1] += v * attD[g];
                }
        #pragma unroll
        for (int o = 1; o <= 2; o <<= 1)
            #pragma unroll
            for (int mt = 0; mt < 2; mt++)
                #pragma unroll
                for (int q = 0; q < 2; q++) {
                    sS[mt][q] += __shfl_xor_sync(0xffffffffu, sS[mt][q], o);
                    sD[mt][q] += __shfl_xor_sync(0xffffffffu, sD[mt][q], o);
                }
        if (cq == 0) {
            int j = (n0 >> 6) + wn;
            #pragma unroll
            for (int mt = 0; mt < 2; mt++)
                #pragma unroll
                for (int q = 0; q < 2; q++) {
                    int row = m0 + wm * 32 + mt * 16 + r + q * 8;
                    ASP[(size_t)j * M + row] = sS[mt][q];
                    ADP[(size_t)j * M + row] = sD[mt][q];
                }
        }
    }

    #pragma unroll
    for (int mt = 0; mt < 2; mt++) {
        int mrow = m0 + wm * 32 + mt * 16 + r;
        #pragma unroll
        for (int nt = 0; nt < 8; nt++) {
            int ncol = n0 + wn * 64 + nt * 8 + cq * 2;
            float* ac = acc[mt][nt];
            float2 v0 = make_float2(ac[0], ac[1]);
            float2 v1 = make_float2(ac[2], ac[3]);
            if (bias) {
                float b0 = bias[ncol], b1 = bias[ncol + 1];
                v0.x += b0; v0.y += b1; v1.x += b0; v1.y += b1;
            }
            if (ACT == 1) {
                v0.x = fmaxf(v0.x, 0.f); v0.y = fmaxf(v0.y, 0.f);
                v1.x = fmaxf(v1.x, 0.f); v1.y = fmaxf(v1.y, 0.f);
            }
            if (HALF_OUT) {
                __half* Ch = (__half*)Cv;
                *(__half2*)(Ch + (size_t)mrow * ldc + ncol) = __floats2half2_rn(v0.x, v0.y);
                *(__half2*)(Ch + (size_t)(mrow + 8) * ldc + ncol) = __floats2half2_rn(v1.x, v1.y);
            } else {
                float* Cf = (float*)Cv;
                *(float2*)(Cf + (size_t)mrow * ldc + ncol) = v0;
                *(float2*)(Cf + (size_t)(mrow + 8) * ldc + ncol) = v1;
            }
        }
    }
}

// ---------------- asad reduce ----------------
__global__ void asad_reduce_k(const float* __restrict__ ASP, const float* __restrict__ ADP,
                              float* __restrict__ as_, float* __restrict__ ad_)
{
    int idx = blockIdx.x * 256 + threadIdx.x;
    int row = idx >> 3, h = idx & 7;
    float s = 0.f, d = 0.f;
    #pragma unroll
    for (int j = 4 * h; j < 4 * h + 4; j++) {
        s += ASP[(size_t)j * MTOT + row];
        d += ADP[(size_t)j * MTOT + row];
    }
    as_[row * 8 + h] = s;
    ad_[row * 8 + h] = d;
}

// ---------------- sparse GAT aggregation (fp16, HFMA2, 4 accumulator banks) ----------------
__global__ void __launch_bounds__(256) gat_agg_k(
    const __half* __restrict__ hb, const float* __restrict__ as_,
    const float* __restrict__ ad_, const int* __restrict__ nbr,
    const int* __restrict__ cnt, const float* __restrict__ bias,
    float* __restrict__ y, __half* __restrict__ yh)
{
    __shared__ int    s_nbr[NBCAP];
    __shared__ float  s_alpha[HH][NBCAP];
    __shared__ __half2 s_ah[HH][NBCAP];
    __shared__ float  s_inv[HH];
    __shared__ float  s_red[HH][DD];
    int bt  = blockIdx.x;
    int b   = bt >> 10;
    int tid = threadIdx.x;
    int nc  = cnt[bt];
    for (int j = tid; j < nc; j += 256) s_nbr[j] = nbr[(size_t)bt * NBCAP + j];
    __syncthreads();

    for (int j = tid; j < nc; j += 256) {
        int s = s_nbr[j];
        const float* ap = as_ + (size_t)(b * NNODE + s) * HH;
        #pragma unroll
        for (int h = 0; h < HH; h++) {
            float e = ad_[bt * HH + h] + ap[h];
            e = e >= 0.f ? e : 0.2f * e;
            s_alpha[h][j] = __expf(e);
        }
    }
    __syncthreads();

    int h    = tid >> 5;
    int lane = tid & 31;
    {
        float sum = 0.f;
        for (int j = lane; j < nc; j += 32) sum += s_alpha[h][j];
        #pragma unroll
        for (int o = 16; o; o >>= 1) sum += __shfl_xor_sync(0xffffffffu, sum, o);
        if (lane == 0) s_inv[h] = 1.f / (8.f * sum);
    }
    __syncthreads();
    for (int j = tid; j < nc; j += 256) {
        #pragma unroll
        for (int hh = 0; hh < HH; hh++) {
            float w = s_alpha[hh][j] * s_inv[hh];
            s_ah[hh][j] = __float2half2_rn(w);
        }
    }
    __syncthreads();

    // gather: 4 edges/iter into 4 independent half2 accumulator banks
    const __half* hbase = hb + (size_t)b * NNODE * (HH * DD) + h * DD + lane * 8;
    __half2 acc[4][4];
    #pragma unroll
    for (int u = 0; u < 4; u++)
        #pragma unroll
        for (int i = 0; i < 4; i++) acc[u][i] = __floats2half2_rn(0.f, 0.f);
    int j = 0;
    for (; j + 4 <= nc; j += 4) {
        #pragma unroll
        for (int u = 0; u < 4; u++) {
            __half2 w = s_ah[h][j + u];
            float4 rv = *(const float4*)(hbase + (size_t)s_nbr[j + u] * (HH * DD));
            const __half2* p = (const __half2*)&rv;
            #pragma unroll
            for (int i = 0; i < 4; i++)
                acc[u][i] = __hfma2(p[i], w, acc[u][i]);
        }
    }
    for (; j < nc; j++) {
        __half2 w = s_ah[h][j];
        float4 rv = *(const float4*)(hbase + (size_t)s_nbr[j] * (HH * DD));
        const __half2* p = (const __half2*)&rv;
        #pragma unroll
        for (int i = 0; i < 4; i++)
            acc[0][i] = __hfma2(p[i], w, acc[0][i]);
    }
    {
        #pragma unroll
        for (int i = 0; i < 4; i++) {
            float2 f0 = __half22float2(acc[0][i]);
            float2 f1 = __half22float2(acc[1][i]);
            float2 f2 = __half22float2(acc[2][i]);
            float2 f3 = __half22float2(acc[3][i]);
            float2 r;
            r.x = (f0.x + f1.x) + (f2.x + f3.x);
            r.y = (f0.y + f1.y) + (f2.y + f3.y);
            *(float2*)&s_red[h][lane * 8 + 2 * i] = r;
        }
    }
    __syncthreads();

    {
        int c = tid;
        float v = bias[c];
        #pragma unroll
        for (int hh = 0; hh < HH; hh++) v += s_red[hh][c];
        y[(size_t)bt * DD + c] = v;
        yh[(size_t)bt * DD + c] = __float2half_rn(v);
    }
}

// ---------------- sparse masked attention: two-pass, ILP both passes ----------------
__global__ void __launch_bounds__(256) attn_sparse_k(
    const __half* __restrict__ QKV, const int* __restrict__ nbr,
    const int* __restrict__ cnt, __half* __restrict__ Om)
{
    __shared__ int   s_nbr[NBCAP];
    __shared__ float s_w[HH][NBCAP];
    __shared__ float s_winv[HH];
    int bt  = blockIdx.x;
    int b   = bt >> 10;
    int tid = threadIdx.x;
    int nc  = cnt[bt];
    for (int j = tid; j < nc; j += 256) s_nbr[j] = nbr[(size_t)bt * NBCAP + j];
    __syncthreads();
    int h = tid >> 5, lane = tid & 31;
    const int LD3 = 3 * DD;

    unsigned qh[16];
    {
        const uint4* qp = (const uint4*)(QKV + (size_t)bt * LD3 + h * DHH);
        const __half2 sc2 = __floats2half2_rn(0.17677669529663687f, 0.17677669529663687f);
        #pragma unroll
        for (int i = 0; i < 4; i++) {
            uint4 v = qp[i];
            unsigned* u = (unsigned*)&v;
            #pragma unroll
            for (int k = 0; k < 4; k++) {
                __half2 hv = __hmul2(*(__half2*)&u[k], sc2);
                qh[i * 4 + k] = *(unsigned*)&hv;
            }
        }
    }

    // pass 1: lane = edge, 2 edges in flight
    float aw = 0.f;
    int j = lane;
    for (; j + 32 < nc; j += 64) {
        int s0 = s_nbr[j], s1 = s_nbr[j + 32];
        const uint4* kp0 = (const uint4*)(QKV + (size_t)(b * NNODE + s0) * LD3 + DD + h * DHH);
        const uint4* kp1 = (const uint4*)(QKV + (size_t)(b * NNODE + s1) * LD3 + DD + h * DHH);
        __half2 a0 = __floats2half2_rn(0.f, 0.f);
        __half2 a1 = __floats2half2_rn(0.f, 0.f);
        #pragma unroll
        for (int i = 0; i < 4; i++) {
            uint4 v0 = kp0[i], v1 = kp1[i];
            unsigned* u0 = (unsigned*)&v0;
            unsigned* u1 = (unsigned*)&v1;
            #pragma unroll
            for (int k = 0; k < 4; k++) {
                a0 = __hfma2(*(__half2*)&u0[k], *(__half2*)&qh[i * 4 + k], a0);
                a1 = __hfma2(*(__half2*)&u1[k], *(__half2*)&qh[i * 4 + k], a1);
            }
        }
        float2 f0 = __half22float2(a0);
        float2 f1 = __half22float2(a1);
        float w0 = __expf(f0.x + f0.y);
        float w1 = __expf(f1.x + f1.y);
        s_w[h][j] = w0;
        s_w[h][j + 32] = w1;
        aw += w0 + w1;
    }
    for (; j < nc; j += 32) {
        int s = s_nbr[j];
        const uint4* kp = (const uint4*)(QKV + (size_t)(b * NNODE + s) * LD3 + DD + h * DHH);
        __half2 acc2 = __floats2half2_rn(0.f, 0.f);
        #pragma unroll
        for (int i = 0; i < 4; i++) {
            uint4 v = kp[i];
            unsigned* u = (unsigned*)&v;
            #pragma unroll
            for (int k = 0; k < 4; k++)
                acc2 = __hfma2(*(__half2*)&u[k], *(__half2*)&qh[i * 4 + k], acc2);
        }
        float2 f = __half22float2(acc2);
        float w = __expf(f.x + f.y);
        s_w[h][j] = w;
        aw += w;
    }
    #pragma unroll
    for (int o = 16; o; o >>= 1) aw += __shfl_xor_sync(0xffffffffu, aw, o);
    if (lane == 0) s_winv[h] = 1.f / aw;
    __syncwarp();

    // pass 2: lane = channel, 4 independent accumulators
    const __half* vbase = QKV + (size_t)b * NNODE * LD3 + 2 * DD + h * DHH + lane;
    float av0 = 0.f, av1 = 0.f, av2 = 0.f, av3 = 0.f;
    j = 0;
    for (; j + 4 <= nc; j += 4) {
        av0 = fmaf(s_w[h][j],     __half2float(vbase[(size_t)s_nbr[j]     * LD3]), av0);
        av1 = fmaf(s_w[h][j + 1], __half2float(vbase[(size_t)s_nbr[j + 1] * LD3]), av1);
        av2 = fmaf(s_w[h][j + 2], __half2float(vbase[(size_t)s_nbr[j + 2] * LD3]), av2);
        av3 = fmaf(s_w[h][j + 3], __half2float(vbase[(size_t)s_nbr[j + 3] * LD3]), av3);
    }
    for (; j < nc; j++)
        av0 = fmaf(s_w[h][j], __half2float(vbase[(size_t)s_nbr[j] * LD3]), av0);
    float accv = (av0 + av1) + (av2 + av3);
    Om[(size_t)bt * DD + h * DHH + lane] = __float2half_rn(accv * s_winv[h]);
}

// ---------------- layernorm: warp per row ----------------
// MODE 0: out = LN(a + bsrc)            MODE 1: out = LN(a + relu(bsrc))
// MODE 2: out = LN(a + sum4(PART) + bias2)   MODE 3: out = LN(a + sum2(PART) + bias2)
template<int MODE, int WRITEH>
__global__ void __launch_bounds__(256) ln_warp_k(
    const float* __restrict__ a, const float* __restrict__ bsrc,
    const float* __restrict__ gam, const float* __restrict__ bet,
    float* __restrict__ out, __half* __restrict__ outh,
    const float* __restrict__ bias2)
{
    int row  = blockIdx.x * 8 + (threadIdx.x >> 5);
    int lane = threadIdx.x & 31;
    size_t base = (size_t)row * DD;
    float v[8];
    float sum = 0.f;
    #pragma unroll
    for (int p = 0; p < 2; p++) {
        int c = lane * 4 + p * 128;
        float4 av = *(const float4*)(a + base + c);
        float4 bv;
        if (MODE == 2 || MODE == 3) {
            float4 p0 = *(const float4*)(bsrc + base + c);
            float4 p1 = *(const float4*)(bsrc + (size_t)MTOT * DD + base + c);
            float4 bb2 = *(const float4*)(bias2 + c);
            bv.x = p0.x + p1.x + bb2.x;
            bv.y = p0.y + p1.y + bb2.y;
            bv.z = p0.z + p1.z + bb2.z;
            bv.w = p0.w + p1.w + bb2.w;
            if (MODE == 2) {
                float4 p2 = *(const float4*)(bsrc + (size_t)2 * MTOT * DD + base + c);
                float4 p3 = *(const float4*)(bsrc + (size_t)3 * MTOT * DD + base + c);
                bv.x += p2.x + p3.x;
                bv.y += p2.y + p3.y;
                bv.z += p2.z + p3.z;
                bv.w += p2.w + p3.w;
            }
        } else {
            bv = *(const float4*)(bsrc + base + c);
            if (MODE == 1) {
                bv.x = fmaxf(bv.x, 0.f); bv.y = fmaxf(bv.y, 0.f);
                bv.z = fmaxf(bv.z, 0.f); bv.w = fmaxf(bv.w, 0.f);
            }
        }
        v[p*4+0] = av.x + bv.x; v[p*4+1] = av.y + bv.y;
        v[p*4+2] = av.z + bv.z; v[p*4+3] = av.w + bv.w;
        sum += v[p*4+0] + v[p*4+1] + v[p*4+2] + v[p*4+3];
    }
    #pragma unroll
    for (int o = 16; o; o >>= 1) sum += __shfl_xor_sync(0xffffffffu, sum, o);
    float mean = sum * (1.f / DD);
    float var = 0.f;
    #pragma unroll
    for (int i = 0; i < 8; i++) { float d = v[i] - mean; var += d * d; }
    #pragma unroll
    for (int o = 16; o; o >>= 1) var += __shfl_xor_sync(0xffffffffu, var, o);
    float rstd = rsqrtf(var * (1.f / DD) + 1e-5f);
    #pragma unroll
    for (int p = 0; p < 2; p++) {
        int c = lane * 4 + p * 128;
        float4 g = *(const float4*)(gam + c);
        float4 bb = *(const float4*)(bet + c);
        float4 o4;
        o4.x = (v[p*4+0] - mean) * rstd * g.x + bb.x;
        o4.y = (v[p*4+1] - mean) * rstd * g.y + bb.y;
        o4.z = (v[p*4+2] - mean) * rstd * g.z + bb.z;
        o4.w = (v[p*4+3] - mean) * rstd * g.w + bb.w;
        *(float4*)(out + base + c) = o4;
        if (WRITEH) {
            __half2 h0 = __floats2half2_rn(o4.x, o4.y);
            __half2 h1 = __floats2half2_rn(o4.z, o4.w);
            *(uint2*)(outh + base + c) = make_uint2(*(unsigned*)&h0, *(unsigned*)&h1);
        }
    }
}

extern "C" void kernel_launch(void* const* d_in, const int* in_sizes, int n_in,
                              void* d_out, int out_size)
{
    const float* emb  = (const float*)d_in[0];
    const int*   mask = (const int*)  d_in[2];
    const float* gatW = (const float*)d_in[4];
    const float* attS = (const float*)d_in[5];
    const float* attD = (const float*)d_in[6];
    const float* gatB = (const float*)d_in[7];
    const float* glnS = (const float*)d_in[8];
    const float* glnB = (const float*)d_in[9];
    const float* Wq = (const float*)d_in[10], *bq = (const float*)d_in[11];
    const float* Wk = (const float*)d_in[12], *bk = (const float*)d_in[13];
    const float* Wv = (const float*)d_in[14], *bv = (const float*)d_in[15];
    const float* Wo = (const float*)d_in[16], *bo = (const float*)d_in[17];
    const float* W1 = (const float*)d_in[18], *b1 = (const float*)d_in[19];
    const float* W2 = (const float*)d_in[20], *b2 = (const float*)d_in[21];
    const float* l1s = (const float*)d_in[22], *l1b = (const float*)d_in[23];
    const float* l2s = (const float*)d_in[24], *l2b = (const float*)d_in[25];
    float* out = (float*)d_out;

    float *XC,*AS,*AD,*ASP,*ADP,*BQKV,*Y,*PART;
    __half *XCH,*EMBH,*HBH,*QKVH,*WQKVH,*GATWH,*WOH,*W1H,*W2H,*AOH,*YH,*FFH;
    unsigned* BITS; int *NBR,*CNT;
    cudaGetSymbolAddress((void**)&XC, g_XC);
    cudaGetSymbolAddress((void**)&XCH, g_XCH);
    cudaGetSymbolAddress((void**)&EMBH, g_EMBH);
    cudaGetSymbolAddress((void**)&HBH, g_HBH);
    cudaGetSymbolAddress((void**)&AS, g_AS);
    cudaGetSymbolAddress((void**)&AD, g_AD);
    cudaGetSymbolAddress((void**)&ASP, g_ASP);
    cudaGetSymbolAddress((void**)&ADP, g_ADP);
    cudaGetSymbolAddress((void**)&QKVH, g_QKVH);
    cudaGetSymbolAddress((void**)&WQKVH, g_WQKVH);
    cudaGetSymbolAddress((void**)&BQKV, g_BQKV);
    cudaGetSymbolAddress((void**)&GATWH, g_GATWH);
    cudaGetSymbolAddress((void**)&WOH, g_WOH);
    cudaGetSymbolAddress((void**)&W1H, g_W1H);
    cudaGetSymbolAddress((void**)&W2H, g_W2H);
    cudaGetSymbolAddress((void**)&AOH, g_AOH);
    cudaGetSymbolAddress((void**)&Y,  g_Y);
    cudaGetSymbolAddress((void**)&YH, g_YH);
    cudaGetSymbolAddress((void**)&FFH, g_FFH);
    cudaGetSymbolAddress((void**)&PART, g_PART);
    cudaGetSymbolAddress((void**)&BITS, g_BITS);
    cudaGetSymbolAddress((void**)&NBR, g_NBR);
    cudaGetSymbolAddress((void**)&CNT, g_CNT);

    const int M = MTOT;

    pack_adj_k<<<(BB*32*NNODE)/256, 256>>>(mask, BITS);
    build_nbr_k<<<(MTOT)/256, 256>>>(BITS, NBR, CNT);
    pack_qkv_k<<<(LTN*DD*3*DD + 255)/256, 256>>>(Wq, Wk, Wv, bq, bk, bv, WQKVH, BQKV);
    cvt_all_k<<<(CV_TOT/4 + 255)/256, 256>>>(emb, gatW, Wo, W1, W2);

    // ---- GAT stack ----
    const __half* x = EMBH;
    for (int l = 0; l < LGN; l++) {
        hgemm_k<true,0,1,1,1><<<dim3((HH*DD)/128, M/128), 256>>>(
            M, HH*DD, DD, x, DD, GATWH + (size_t)l*HH*DD*DD, DD,
            HBH, HH*DD, nullptr, attS + l*HH*DD, attD + l*HH*DD, ASP, ADP);
        asad_reduce_k<<<(MTOT*8)/256, 256>>>(ASP, ADP, AS, AD);
        gat_agg_k<<<M, 256>>>(HBH, AS, AD, NBR, CNT, gatB + l*DD, Y, YH);
        x = YH;
    }
    ln_warp_k<1,1><<<M/8, 256>>>(emb, Y, glnS, glnB, XC, XCH, nullptr);

    // ---- transformer layers ----
    for (int l = 0; l < LTN; l++) {
        hgemm_k<false,0,1,0,1><<<dim3((3*DD)/128, M/128), 256>>>(
            M, 3*DD, DD, XCH, DD, WQKVH + (size_t)l*DD*3*DD, 3*DD, QKVH, 3*DD,
            BQKV + l*3*DD, nullptr, nullptr, nullptr, nullptr);
        attn_sparse_k<<<M, 256>>>(QKVH, NBR, CNT, AOH);
        // Wo: split-K=2 into PART; LN consumes 2 partials (MODE 3)
        hgemm_k<false,0,0,0,2><<<dim3(DD/128, M/128, 2), 256>>>(
            M, DD, DD, AOH, DD, WOH + (size_t)l*DD*DD, DD, PART, DD,
            nullptr, nullptr, nullptr, nullptr, nullptr);
        ln_warp_k<3,1><<<M/8, 256>>>(XC, PART, l1s + l*DD, l1b + l*DD, XC, XCH, bo + l*DD);
        hgemm_k<false,1,1,0,1><<<dim3(DFFX/128, M/128), 256>>>(
            M, DFFX, DD, XCH, DD, W1H + (size_t)l*DD*DFFX, DFFX, FFH, DFFX,
            b1 + l*DFFX, nullptr, nullptr, nullptr, nullptr);
        // FFN2: split-K=4 into PART; LN consumes 4 partials (MODE 2)
        hgemm_k<false,0,0,0,SPLK><<<dim3(DD/128, M/128, SPLK), 256>>>(
            M, DD, DFFX, FFH, DFFX, W2H + (size_t)l*DFFX*DD, DD, PART, DD,
            nullptr, nullptr, nullptr, nullptr, nullptr);
        if (l == LTN - 1)
            ln_warp_k<2,0><<<M/8, 256>>>(XC, PART, l2s + l*DD, l2b + l*DD, out, nullptr, b2 + l*DD);
        else
            ln_warp_k<2,1><<<M/8, 256>>>(XC, PART, l2s + l*DD, l2b + l*DD, XC, XCH, b2 + l*DD);
    }
}

// round 15
// speedup vs baseline: 1.0119x; 1.0119x over previous
#include <cuda_runtime.h>
#include <cuda_fp16.h>
#include <math.h>

// ---------------- dims ----------------
#define BB    8
#define NNODE 1024
#define DD    256
#define HH    8
#define DHH   32
#define DFFX  1024
#define LGN   2
#define LTN   2
#define NBCAP 256
#define MTOT  (BB*NNODE)
#define SPLK  4

// ---------------- scratch (device globals; no runtime allocation) ----------------
__device__ float                 g_XC[MTOT*DD];
__device__ __align__(16) __half  g_XCH[MTOT*DD];
__device__ __align__(16) __half  g_EMBH[MTOT*DD];
__device__ __align__(16) __half  g_HBH[MTOT*HH*DD];
__device__ float                 g_AS[MTOT*HH];
__device__ float                 g_AD[MTOT*HH];
__device__ float                 g_ASP[32*MTOT];
__device__ float                 g_ADP[32*MTOT];
__device__ __align__(16) __half  g_QKVH[MTOT*3*DD];
__device__ __align__(16) __half  g_WQKVH[LTN*DD*3*DD];
__device__ float                 g_BQKV[LTN*3*DD];
__device__ __align__(16) __half  g_GATWH[LGN*HH*DD*DD];
__device__ __align__(16) __half  g_WOH[LTN*DD*DD];
__device__ __align__(16) __half  g_W1H[LTN*DD*DFFX];
__device__ __align__(16) __half  g_W2H[LTN*DFFX*DD];
__device__ __align__(16) __half  g_AOH[MTOT*DD];
__device__ float                 g_Y [MTOT*DD];
__device__ __align__(16) __half  g_YH[MTOT*DD];
__device__ __align__(16) __half  g_FFH[MTOT*DFFX];
__device__ float                 g_PART[SPLK*MTOT*DD];
__device__ unsigned              g_BITS[MTOT*(NNODE/32)];
__device__ int                   g_NBR[MTOT*NBCAP];
__device__ int                   g_CNT[MTOT];

// ---------------- helpers ----------------
__device__ __forceinline__ void mma_f16(float* c, const unsigned* a, const unsigned* b) {
    asm volatile(
        "mma.sync.aligned.m16n8k16.row.col.f32.f16.f16.f32 "
        "{%0,%1,%2,%3}, {%4,%5,%6,%7}, {%8,%9}, {%0,%1,%2,%3};\n"
        : "+f"(c[0]), "+f"(c[1]), "+f"(c[2]), "+f"(c[3])
        : "r"(a[0]), "r"(a[1]), "r"(a[2]), "r"(a[3]), "r"(b[0]), "r"(b[1]));
}

__device__ __forceinline__ unsigned saddr(const void* p) {
    return (unsigned)__cvta_generic_to_shared(p);
}
__device__ __forceinline__ void cp16(unsigned dst, const void* src) {
    asm volatile("cp.async.cg.shared.global [%0], [%1], 16;\n" :: "r"(dst), "l"(src));
}
__device__ __forceinline__ void cp_commit() {
    asm volatile("cp.async.commit_group;\n" ::: "memory");
}
template<int N>
__device__ __forceinline__ void cp_wait() {
    asm volatile("cp.async.wait_group %0;\n" :: "n"(N) : "memory");
}
__device__ __forceinline__ void ldsm4(unsigned& r0, unsigned& r1, unsigned& r2, unsigned& r3,
                                      unsigned addr) {
    asm volatile("ldmatrix.sync.aligned.m8n8.x4.shared.b16 {%0,%1,%2,%3}, [%4];"
                 : "=r"(r0), "=r"(r1), "=r"(r2), "=r"(r3) : "r"(addr));
}
__device__ __forceinline__ void ldsm4t(unsigned& r0, unsigned& r1, unsigned& r2, unsigned& r3,
                                       unsigned addr) {
    asm volatile("ldmatrix.sync.aligned.m8n8.x4.trans.shared.b16 {%0,%1,%2,%3}, [%4];"
                 : "=r"(r0), "=r"(r1), "=r"(r2), "=r"(r3) : "r"(addr));
}

// ---------------- adjacency pack ----------------
__global__ void pack_adj_k(const int* __restrict__ mask, unsigned* __restrict__ bits) {
    int idx = blockIdx.x * blockDim.x + threadIdx.x;
    int t  = idx & (NNODE - 1);
    int sw = (idx >> 10) & 31;
    int b  = idx >> 15;
    const int* mp = mask + ((size_t)b * NNODE + (size_t)sw * 32) * NNODE + t;
    unsigned w = 0;
    #pragma unroll
    for (int i = 0; i < 32; i++)
        if (mp[(size_t)i * NNODE] > 0) w |= (1u << i);
    int s0 = sw * 32;
    if (t >= s0 && t < s0 + 32) w |= (1u << (t - s0));
    bits[(b * NNODE + t) * 32 + sw] = w;
}

// ---------------- neighbor list build ----------------
__global__ void build_nbr_k(const unsigned* __restrict__ bits,
                            int* __restrict__ nbr, int* __restrict__ cnt) {
    int bt = blockIdx.x * blockDim.x + threadIdx.x;
    if (bt >= MTOT) return;
    const unsigned* bw = bits + (size_t)bt * 32;
    int* np = nbr + (size_t)bt * NBCAP;
    int c = 0;
    #pragma unroll 4
    for (int w = 0; w < 32; w++) {
        unsigned m = bw[w];
        while (m) {
            int bit = __ffs(m) - 1;
            m &= m - 1;
            if (c < NBCAP) np[c] = w * 32 + bit;
            c++;
        }
    }
    cnt[bt] = c < NBCAP ? c : NBCAP;
}

// ---------------- fused prep: fp32->fp16 converts + QKV weight/bias pack ----------------
#define CV_N1 (MTOT*DD)
#define CV_N2 (LGN*HH*DD*DD)
#define CV_N3 (LTN*DD*DD)
#define CV_N4 (LTN*DD*DFFX)
#define CV_N5 (LTN*DFFX*DD)
#define CV_N6 (LTN*DD*3*DD)
#define CV_TOT (CV_N1+CV_N2+CV_N3+CV_N4+CV_N5+CV_N6)

__global__ void cvt_prep_k(const float* __restrict__ emb, const float* __restrict__ gatW,
                           const float* __restrict__ Wo, const float* __restrict__ W1,
                           const float* __restrict__ W2,
                           const float* __restrict__ Wq, const float* __restrict__ Wk,
                           const float* __restrict__ Wv, const float* __restrict__ bq,
                           const float* __restrict__ bk, const float* __restrict__ bv)
{
    int i = (blockIdx.x * 256 + threadIdx.x) * 4;
    if (i >= CV_TOT) return;
    if (i >= CV_N1 + CV_N2 + CV_N3 + CV_N4 + CV_N5) {
        // QKV pack range: interleave Wq|Wk|Wv into [l][k][768] fp16 + bias fp32
        int idx = i - (CV_N1 + CV_N2 + CV_N3 + CV_N4 + CV_N5);
        int n = idx % (3 * DD);          // 4-aligned, stays within one source
        int k = (idx / (3 * DD)) % DD;
        int l = idx / (3 * DD * DD);
        const float* src; int col;
        if (n < DD)          { src = Wq; col = n; }
        else if (n < 2 * DD) { src = Wk; col = n - DD; }
        else                 { src = Wv; col = n - 2 * DD; }
        float4 v = *(const float4*)(src + ((size_t)l * DD + k) * DD + col);
        *(__half2*)(g_WQKVH + idx)     = __floats2half2_rn(v.x, v.y);
        *(__half2*)(g_WQKVH + idx + 2) = __floats2half2_rn(v.z, v.w);
        if (k == 0) {
            const float* bsrc = (n < DD) ? bq : (n < 2 * DD ? bk : bv);
            float4 bvv = *(const float4*)(bsrc + l * DD + col);
            *(float4*)(g_BQKV + l * 3 * DD + n) = bvv;
        }
        return;
    }
    const float* src; __half* dst; int off;
    if (i < CV_N1)                         { src = emb;  dst = g_EMBH;  off = i; }
    else if (i < CV_N1 + CV_N2)            { src = gatW; dst = g_GATWH; off = i - CV_N1; }
    else if (i < CV_N1 + CV_N2 + CV_N3)    { src = Wo;   dst = g_WOH;   off = i - CV_N1 - CV_N2; }
    else if (i < CV_N1 + CV_N2 + CV_N3 + CV_N4)
                                           { src = W1;   dst = g_W1H;   off = i - CV_N1 - CV_N2 - CV_N3; }
    else                                   { src = W2;   dst = g_W2H;   off = i - CV_N1 - CV_N2 - CV_N3 - CV_N4; }
    float4 v = *(const float4*)(src + off);
    *(__half2*)(dst + off)     = __floats2half2_rn(v.x, v.y);
    *(__half2*)(dst + off + 2) = __floats2half2_rn(v.z, v.w);
}

// ---------------- fp16 tensor-core GEMM: 2-stage cp.async + ldmatrix ----------------
template<bool BT, int ACT, int HALF_OUT, int ASAD, int SPLITZ>
__global__ void __launch_bounds__(256) hgemm_k(
    int M, int Ncol, int K,
    const __half* __restrict__ A, int lda,
    const __half* __restrict__ B, int ldb,
    void* __restrict__ Cv, int ldc,
    const float* __restrict__ bias,
    const float* __restrict__ attS, const float* __restrict__ attD,
    float* __restrict__ ASP, float* __restrict__ ADP)
{
    if (SPLITZ > 1) {
        int Kc = K / SPLITZ;
        A += (size_t)blockIdx.z * Kc;
        B += (size_t)blockIdx.z * Kc * ldb;
        Cv = (void*)((float*)Cv + (size_t)blockIdx.z * M * Ncol);
        K = Kc;
    }
    __shared__ __align__(16) __half sA[2][128 * 24];
    __shared__ __align__(16) __half sB[2][3072];
    const int tid  = threadIdx.x;
    const int lane = tid & 31, wid = tid >> 5;
    const int wm = wid & 3, wn = wid >> 2;
    const int m0 = blockIdx.y * 128, n0 = blockIdx.x * 128;
    const int r = lane >> 2, cq = lane & 3;

    float acc[2][8][4];
    #pragma unroll
    for (int mt = 0; mt < 2; mt++)
        #pragma unroll
        for (int nt = 0; nt < 8; nt++)
            #pragma unroll
            for (int u = 0; u < 4; u++) acc[mt][nt][u] = 0.f;

    const int T = K / 16;

    auto loadT = [&](int st, int k0) {
        {
            int m = tid >> 1, c = tid & 1;
            cp16(saddr(&sA[st][m * 24 + c * 8]), A + (size_t)(m0 + m) * lda + k0 + c * 8);
        }
        if (BT) {
            int n = tid >> 1, c = tid & 1;
            cp16(saddr(&sB[st][n * 24 + c * 8]), B + (size_t)(n0 + n) * ldb + k0 + c * 8);
        } else {
            int kk = tid >> 4, c = tid & 15;
            cp16(saddr(&sB[st][kk * 136 + c * 8]), B + (size_t)(k0 + kk) * ldb + n0 + c * 8);
        }
        cp_commit();
    };

    loadT(0, 0);
    for (int t = 0; t < T; t++) {
        if (t + 1 < T) { loadT((t + 1) & 1, (t + 1) * 16); cp_wait<1>(); }
        else           { cp_wait<0>(); }
        __syncthreads();
        const int st = t & 1;

        unsigned af[2][4], bf[8][2];
        #pragma unroll
        for (int mt = 0; mt < 2; mt++) {
            int mrow = wm * 32 + mt * 16;
            unsigned addr = saddr(&sA[st][(mrow + (lane & 15)) * 24 + (lane >> 4) * 8]);
            ldsm4(af[mt][0], af[mt][1], af[mt][2], af[mt][3], addr);
        }
        #pragma unroll
        for (int p = 0; p < 4; p++) {
            int nb = wn * 64 + p * 16;
            if (BT) {
                int row = nb + (lane & 7) + ((lane >> 4) << 3);
                int col = ((lane >> 3) & 1) * 8;
                unsigned addr = saddr(&sB[st][row * 24 + col]);
                ldsm4(bf[2 * p][0], bf[2 * p][1], bf[2 * p + 1][0], bf[2 * p + 1][1], addr);
            } else {
                int krow = (lane & 7) + (((lane >> 3) & 1) << 3);
                int coln = nb + (lane >> 4) * 8;
                unsigned addr = saddr(&sB[st][krow * 136 + coln]);
                ldsm4t(bf[2 * p][0], bf[2 * p][1], bf[2 * p + 1][0], bf[2 * p + 1][1], addr);
            }
        }
        #pragma unroll
        for (int mt = 0; mt < 2; mt++)
            #pragma unroll
            for (int nt = 0; nt < 8; nt++)
                mma_f16(acc[mt][nt], af[mt], bf[nt]);
        __syncthreads();
    }

    if (ASAD) {
        float sS[2][2] = {{0,0},{0,0}}, sD[2][2] = {{0,0},{0,0}};
        #pragma unroll
        for (int mt = 0; mt < 2; mt++)
            #pragma unroll
            for (int nt = 0; nt < 8; nt++)
                #pragma unroll
                for (int u = 0; u < 4; u++) {
                    int g = n0 + wn * 64 + nt * 8 + cq * 2 + (u & 1);
                    float v = acc[mt][nt][u];
                    sS[mt][u >> 1] += v * attS[g];
                    sD[mt][u >> 1] += v * attD[g];
                }
        #pragma unroll
        for (int o = 1; o <= 2; o <<= 1)
            #pragma unroll
            for (int mt = 0; mt < 2; mt++)
                #pragma unroll
                for (int q = 0; q < 2; q++) {
                    sS[mt][q] += __shfl_xor_sync(0xffffffffu, sS[mt][q], o);
                    sD[mt][q] += __shfl_xor_sync(0xffffffffu, sD[mt][q], o);
                }
        if (cq == 0) {
            int j = (n0 >> 6) + wn;
            #pragma unroll
            for (int mt = 0; mt < 2; mt++)
                #pragma unroll
                for (int q = 0; q < 2; q++) {
                    int row = m0 + wm * 32 + mt * 16 + r + q * 8;
                    ASP[(size_t)j * M + row] = sS[mt][q];
                    ADP[(size_t)j * M + row] = sD[mt][q];
                }
        }
    }

    #pragma unroll
    for (int mt = 0; mt < 2; mt++) {
        int mrow = m0 + wm * 32 + mt * 16 + r;
        #pragma unroll
        for (int nt = 0; nt < 8; nt++) {
            int ncol = n0 + wn * 64 + nt * 8 + cq * 2;
            float* ac = acc[mt][nt];
            float2 v0 = make_float2(ac[0], ac[1]);
            float2 v1 = make_float2(ac[2], ac[3]);
            if (bias) {
                float b0 = bias[ncol], b1 = bias[ncol + 1];
                v0.x += b0; v0.y += b1; v1.x += b0; v1.y += b1;
            }
            if (ACT == 1) {
                v0.x = fmaxf(v0.x, 0.f); v0.y = fmaxf(v0.y, 0.f);
                v1.x = fmaxf(v1.x, 0.f); v1.y = fmaxf(v1.y, 0.f);
            }
            if (HALF_OUT) {
                __half* Ch = (__half*)Cv;
                *(__half2*)(Ch + (size_t)mrow * ldc + ncol) = __floats2half2_rn(v0.x, v0.y);
                *(__half2*)(Ch + (size_t)(mrow + 8) * ldc + ncol) = __floats2half2_rn(v1.x, v1.y);
            } else {
                float* Cf = (float*)Cv;
                *(float2*)(Cf + (size_t)mrow * ldc + ncol) = v0;
                *(float2*)(Cf + (size_t)(mrow + 8) * ldc + ncol) = v1;
            }
        }
    }
}

// ---------------- asad reduce ----------------
__global__ void asad_reduce_k(const float* __restrict__ ASP, const float* __restrict__ ADP,
                              float* __restrict__ as_, float* __restrict__ ad_)
{
    int idx = blockIdx.x * 256 + threadIdx.x;
    int row = idx >> 3, h = idx & 7;
    float s = 0.f, d = 0.f;
    #pragma unroll
    for (int j = 4 * h; j < 4 * h + 4; j++) {
        s += ASP[(size_t)j * MTOT + row];
        d += ADP[(size_t)j * MTOT + row];
    }
    as_[row * 8 + h] = s;
    ad_[row * 8 + h] = d;
}

// ---------------- sparse GAT aggregation (fp16, HFMA2, 2 accumulator banks — R13) ----------------
__global__ void __launch_bounds__(256) gat_agg_k(
    const __half* __restrict__ hb, const float* __restrict__ as_,
    const float* __restrict__ ad_, const int* __restrict__ nbr,
    const int* __restrict__ cnt, const float* __restrict__ bias,
    float* __restrict__ y, __half* __restrict__ yh)
{
    __shared__ int    s_nbr[NBCAP];
    __shared__ float  s_alpha[HH][NBCAP];
    __shared__ __half2 s_ah[HH][NBCAP];
    __shared__ float  s_inv[HH];
    __shared__ float  s_red[HH][DD];
    int bt  = blockIdx.x;
    int b   = bt >> 10;
    int tid = threadIdx.x;
    int nc  = cnt[bt];
    for (int j = tid; j < nc; j += 256) s_nbr[j] = nbr[(size_t)bt * NBCAP + j];
    __syncthreads();

    for (int j = tid; j < nc; j += 256) {
        int s = s_nbr[j];
        const float* ap = as_ + (size_t)(b * NNODE + s) * HH;
        #pragma unroll
        for (int h = 0; h < HH; h++) {
            float e = ad_[bt * HH + h] + ap[h];
            e = e >= 0.f ? e : 0.2f * e;
            s_alpha[h][j] = __expf(e);
        }
    }
    __syncthreads();

    int h    = tid >> 5;
    int lane = tid & 31;
    {
        float sum = 0.f;
        for (int j = lane; j < nc; j += 32) sum += s_alpha[h][j];
        #pragma unroll
        for (int o = 16; o; o >>= 1) sum += __shfl_xor_sync(0xffffffffu, sum, o);
        if (lane == 0) s_inv[h] = 1.f / (8.f * sum);
    }
    __syncthreads();
    for (int j = tid; j < nc; j += 256) {
        #pragma unroll
        for (int hh = 0; hh < HH; hh++) {
            float w = s_alpha[hh][j] * s_inv[hh];
            s_ah[hh][j] = __float2half2_rn(w);
        }
    }
    __syncthreads();

    const __half* hbase = hb + (size_t)b * NNODE * (HH * DD) + h * DD + lane * 8;
    __half2 acc0[4], acc1[4];
    #pragma unroll
    for (int i = 0; i < 4; i++) {
        acc0[i] = __floats2half2_rn(0.f, 0.f);
        acc1[i] = __floats2half2_rn(0.f, 0.f);
    }
    int j = 0;
    for (; j + 2 <= nc; j += 2) {
        __half2 w0 = s_ah[h][j];
        __half2 w1 = s_ah[h][j + 1];
        float4 r0 = *(const float4*)(hbase + (size_t)s_nbr[j] * (HH * DD));
        float4 r1 = *(const float4*)(hbase + (size_t)s_nbr[j + 1] * (HH * DD));
        const __half2* p0 = (const __half2*)&r0;
        const __half2* p1 = (const __half2*)&r1;
        #pragma unroll
        for (int i = 0; i < 4; i++) {
            acc0[i] = __hfma2(p0[i], w0, acc0[i]);
            acc1[i] = __hfma2(p1[i], w1, acc1[i]);
        }
    }
    if (j < nc) {
        __half2 w0 = s_ah[h][j];
        float4 r0 = *(const float4*)(hbase + (size_t)s_nbr[j] * (HH * DD));
        const __half2* p0 = (const __half2*)&r0;
        #pragma unroll
        for (int i = 0; i < 4; i++)
            acc0[i] = __hfma2(p0[i], w0, acc0[i]);
    }
    {
        #pragma unroll
        for (int i = 0; i < 2; i++) {
            float2 a0 = __half22float2(acc0[2*i]),   b0 = __half22float2(acc1[2*i]);
            float2 a1 = __half22float2(acc0[2*i+1]), b1 = __half22float2(acc1[2*i+1]);
            *(float4*)&s_red[h][lane * 8 + 4*i] =
                make_float4(a0.x + b0.x, a0.y + b0.y, a1.x + b1.x, a1.y + b1.y);
        }
    }
    __syncthreads();

    {
        int c = tid;
        float v = bias[c];
        #pragma unroll
        for (int hh = 0; hh < HH; hh++) v += s_red[hh][c];
        y[(size_t)bt * DD + c] = v;
        yh[(size_t)bt * DD + c] = __float2half_rn(v);
    }
}

// ---------------- sparse masked attention: two-pass (R13) ----------------
__global__ void __launch_bounds__(256) attn_sparse_k(
    const __half* __restrict__ QKV, const int* __restrict__ nbr,
    const int* __restrict__ cnt, __half* __restrict__ Om)
{
    __shared__ int   s_nbr[NBCAP];
    __shared__ float s_w[HH][NBCAP];
    __shared__ float s_winv[HH];
    int bt  = blockIdx.x;
    int b   = bt >> 10;
    int tid = threadIdx.x;
    int nc  = cnt[bt];
    for (int j = tid; j < nc; j += 256) s_nbr[j] = nbr[(size_t)bt * NBCAP + j];
    __syncthreads();
    int h = tid >> 5, lane = tid & 31;
    const int LD3 = 3 * DD;

    unsigned qh[16];
    {
        const uint4* qp = (const uint4*)(QKV + (size_t)bt * LD3 + h * DHH);
        const __half2 sc2 = __floats2half2_rn(0.17677669529663687f, 0.17677669529663687f);
        #pragma unroll
        for (int i = 0; i < 4; i++) {
            uint4 v = qp[i];
            unsigned* u = (unsigned*)&v;
            #pragma unroll
            for (int k = 0; k < 4; k++) {
                __half2 hv = __hmul2(*(__half2*)&u[k], sc2);
                qh[i * 4 + k] = *(unsigned*)&hv;
            }
        }
    }

    float aw = 0.f;
    for (int j = lane; j < nc; j += 32) {
        int s = s_nbr[j];
        const uint4* kp = (const uint4*)(QKV + (size_t)(b * NNODE + s) * LD3 + DD + h * DHH);
        __half2 acc2 = __floats2half2_rn(0.f, 0.f);
        #pragma unroll
        for (int i = 0; i < 4; i++) {
            uint4 v = kp[i];
            unsigned* u = (unsigned*)&v;
            #pragma unroll
            for (int k = 0; k < 4; k++)
                acc2 = __hfma2(*(__half2*)&u[k], *(__half2*)&qh[i * 4 + k], acc2);
        }
        float2 f = __half22float2(acc2);
        float w = __expf(f.x + f.y);
        s_w[h][j] = w;
        aw += w;
    }
    #pragma unroll
    for (int o = 16; o; o >>= 1) aw += __shfl_xor_sync(0xffffffffu, aw, o);
    if (lane == 0) s_winv[h] = 1.f / aw;
    __syncwarp();

    const __half* vbase = QKV + (size_t)b * NNODE * LD3 + 2 * DD + h * DHH + lane;
    float av0 = 0.f, av1 = 0.f, av2 = 0.f, av3 = 0.f;
    int j = 0;
    for (; j + 4 <= nc; j += 4) {
        av0 = fmaf(s_w[h][j],     __half2float(vbase[(size_t)s_nbr[j]     * LD3]), av0);
        av1 = fmaf(s_w[h][j + 1], __half2float(vbase[(size_t)s_nbr[j + 1] * LD3]), av1);
        av2 = fmaf(s_w[h][j + 2], __half2float(vbase[(size_t)s_nbr[j + 2] * LD3]), av2);
        av3 = fmaf(s_w[h][j + 3], __half2float(vbase[(size_t)s_nbr[j + 3] * LD3]), av3);
    }
    for (; j < nc; j++)
        av0 = fmaf(s_w[h][j], __half2float(vbase[(size_t)s_nbr[j] * LD3]), av0);
    float accv = (av0 + av1) + (av2 + av3);
    Om[(size_t)bt * DD + h * DHH + lane] = __float2half_rn(accv * s_winv[h]);
}

// ---------------- layernorm: warp per row ----------------
// MODE 0: out = LN(a + bsrc)          MODE 1: out = LN(a + relu(bsrc))
// MODE 2: out = LN(a + sum4(PART) + bias2)
template<int MODE, int WRITEH>
__global__ void __launch_bounds__(256) ln_warp_k(
    const float* __restrict__ a, const float* __restrict__ bsrc,
    const float* __restrict__ gam, const float* __restrict__ bet,
    float* __restrict__ out, __half* __restrict__ outh,
    const float* __restrict__ bias2)
{
    int row  = blockIdx.x * 8 + (threadIdx.x >> 5);
    int lane = threadIdx.x & 31;
    size_t base = (size_t)row * DD;
    float v[8];
    float sum = 0.f;
    #pragma unroll
    for (int p = 0; p < 2; p++) {
        int c = lane * 4 + p * 128;
        float4 av = *(const float4*)(a + base + c);
        float4 bv;
        if (MODE == 2) {
            float4 p0 = *(const float4*)(bsrc + base + c);
            float4 p1 = *(const float4*)(bsrc + (size_t)MTOT * DD + base + c);
            float4 p2 = *(const float4*)(bsrc + (size_t)2 * MTOT * DD + base + c);
            float4 p3 = *(const float4*)(bsrc + (size_t)3 * MTOT * DD + base + c);
            float4 bb2 = *(const float4*)(bias2 + c);
            bv.x = p0.x + p1.x + p2.x + p3.x + bb2.x;
            bv.y = p0.y + p1.y + p2.y + p3.y + bb2.y;
            bv.z = p0.z + p1.z + p2.z + p3.z + bb2.z;
            bv.w = p0.w + p1.w + p2.w + p3.w + bb2.w;
        } else {
            bv = *(const float4*)(bsrc + base + c);
            if (MODE == 1) {
                bv.x = fmaxf(bv.x, 0.f); bv.y = fmaxf(bv.y, 0.f);
                bv.z = fmaxf(bv.z, 0.f); bv.w = fmaxf(bv.w, 0.f);
            }
        }
        v[p*4+0] = av.x + bv.x; v[p*4+1] = av.y + bv.y;
        v[p*4+2] = av.z + bv.z; v[p*4+3] = av.w + bv.w;
        sum += v[p*4+0] + v[p*4+1] + v[p*4+2] + v[p*4+3];
    }
    #pragma unroll
    for (int o = 16; o; o >>= 1) sum += __shfl_xor_sync(0xffffffffu, sum, o);
    float mean = sum * (1.f / DD);
    float var = 0.f;
    #pragma unroll
    for (int i = 0; i < 8; i++) { float d = v[i] - mean; var += d * d; }
    #pragma unroll
    for (int o = 16; o; o >>= 1) var += __shfl_xor_sync(0xffffffffu, var, o);
    float rstd = rsqrtf(var * (1.f / DD) + 1e-5f);
    #pragma unroll
    for (int p = 0; p < 2; p++) {
        int c = lane * 4 + p * 128;
        float4 g = *(const float4*)(gam + c);
        float4 bb = *(const float4*)(bet + c);
        float4 o4;
        o4.x = (v[p*4+0] - mean) * rstd * g.x + bb.x;
        o4.y = (v[p*4+1] - mean) * rstd * g.y + bb.y;
        o4.z = (v[p*4+2] - mean) * rstd * g.z + bb.z;
        o4.w = (v[p*4+3] - mean) * rstd * g.w + bb.w;
        *(float4*)(out + base + c) = o4;
        if (WRITEH) {
            __half2 h0 = __floats2half2_rn(o4.x, o4.y);
            __half2 h1 = __floats2half2_rn(o4.z, o4.w);
            *(uint2*)(outh + base + c) = make_uint2(*(unsigned*)&h0, *(unsigned*)&h1);
        }
    }
}

extern "C" void kernel_launch(void* const* d_in, const int* in_sizes, int n_in,
                              void* d_out, int out_size)
{
    const float* emb  = (const float*)d_in[0];
    const int*   mask = (const int*)  d_in[2];
    const float* gatW = (const float*)d_in[4];
    const float* attS = (const float*)d_in[5];
    const float* attD = (const float*)d_in[6];
    const float* gatB = (const float*)d_in[7];
    const float* glnS = (const float*)d_in[8];
    const float* glnB = (const float*)d_in[9];
    const float* Wq = (const float*)d_in[10], *bq = (const float*)d_in[11];
    const float* Wk = (const float*)d_in[12], *bk = (const float*)d_in[13];
    const float* Wv = (const float*)d_in[14], *bv = (const float*)d_in[15];
    const float* Wo = (const float*)d_in[16], *bo = (const float*)d_in[17];
    const float* W1 = (const float*)d_in[18], *b1 = (const float*)d_in[19];
    const float* W2 = (const float*)d_in[20], *b2 = (const float*)d_in[21];
    const float* l1s = (const float*)d_in[22], *l1b = (const float*)d_in[23];
    const float* l2s = (const float*)d_in[24], *l2b = (const float*)d_in[25];
    float* out = (float*)d_out;

    float *XC,*AS,*AD,*ASP,*ADP,*BQKV,*Y,*PART;
    __half *XCH,*EMBH,*HBH,*QKVH,*WQKVH,*GATWH,*WOH,*W1H,*W2H,*AOH,*YH,*FFH;
    unsigned* BITS; int *NBR,*CNT;
    cudaGetSymbolAddress((void**)&XC, g_XC);
    cudaGetSymbolAddress((void**)&XCH, g_XCH);
    cudaGetSymbolAddress((void**)&EMBH, g_EMBH);
    cudaGetSymbolAddress((void**)&HBH, g_HBH);
    cudaGetSymbolAddress((void**)&AS, g_AS);
    cudaGetSymbolAddress((void**)&AD, g_AD);
    cudaGetSymbolAddress((void**)&ASP, g_ASP);
    cudaGetSymbolAddress((void**)&ADP, g_ADP);
    cudaGetSymbolAddress((void**)&QKVH, g_QKVH);
    cudaGetSymbolAddress((void**)&WQKVH, g_WQKVH);
    cudaGetSymbolAddress((void**)&BQKV, g_BQKV);
    cudaGetSymbolAddress((void**)&GATWH, g_GATWH);
    cudaGetSymbolAddress((void**)&WOH, g_WOH);
    cudaGetSymbolAddress((void**)&W1H, g_W1H);
    cudaGetSymbolAddress((void**)&W2H, g_W2H);
    cudaGetSymbolAddress((void**)&AOH, g_AOH);
    cudaGetSymbolAddress((void**)&Y,  g_Y);
    cudaGetSymbolAddress((void**)&YH, g_YH);
    cudaGetSymbolAddress((void**)&FFH, g_FFH);
    cudaGetSymbolAddress((void**)&PART, g_PART);
    cudaGetSymbolAddress((void**)&BITS, g_BITS);
    cudaGetSymbolAddress((void**)&NBR, g_NBR);
    cudaGetSymbolAddress((void**)&CNT, g_CNT);

    const int M = MTOT;

    pack_adj_k<<<(BB*32*NNODE)/256, 256>>>(mask, BITS);
    build_nbr_k<<<(MTOT)/256, 256>>>(BITS, NBR, CNT);
    cvt_prep_k<<<(CV_TOT/4 + 255)/256, 256>>>(emb, gatW, Wo, W1, W2,
                                              Wq, Wk, Wv, bq, bk, bv);

    // ---- GAT stack ----
    const __half* x = EMBH;
    for (int l = 0; l < LGN; l++) {
        hgemm_k<true,0,1,1,1><<<dim3((HH*DD)/128, M/128), 256>>>(
            M, HH*DD, DD, x, DD, GATWH + (size_t)l*HH*DD*DD, DD,
            HBH, HH*DD, nullptr, attS + l*HH*DD, attD + l*HH*DD, ASP, ADP);
        asad_reduce_k<<<(MTOT*8)/256, 256>>>(ASP, ADP, AS, AD);
        gat_agg_k<<<M, 256>>>(HBH, AS, AD, NBR, CNT, gatB + l*DD, Y, YH);
        x = YH;
    }
    ln_warp_k<1,1><<<M/8, 256>>>(emb, Y, glnS, glnB, XC, XCH, nullptr);

    // ---- transformer layers ----
    for (int l = 0; l < LTN; l++) {
        hgemm_k<false,0,1,0,1><<<dim3((3*DD)/128, M/128), 256>>>(
            M, 3*DD, DD, XCH, DD, WQKVH + (size_t)l*DD*3*DD, 3*DD, QKVH, 3*DD,
            BQKV + l*3*DD, nullptr, nullptr, nullptr, nullptr);
        attn_sparse_k<<<M, 256>>>(QKVH, NBR, CNT, AOH);
        hgemm_k<false,0,0,0,1><<<dim3(DD/128, M/128), 256>>>(
            M, DD, DD, AOH, DD, WOH + (size_t)l*DD*DD, DD, Y, DD,
            bo + l*DD, nullptr, nullptr, nullptr, nullptr);
        ln_warp_k<0,1><<<M/8, 256>>>(XC, Y, l1s + l*DD, l1b + l*DD, XC, XCH, nullptr);
        hgemm_k<false,1,1,0,1><<<dim3(DFFX/128, M/128), 256>>>(
            M, DFFX, DD, XCH, DD, W1H + (size_t)l*DD*DFFX, DFFX, FFH, DFFX,
            b1 + l*DFFX, nullptr, nullptr, nullptr, nullptr);
        // FFN2: split-K=4 into PART; LN consumes partials directly (MODE 2)
        hgemm_k<false,0,0,0,SPLK><<<dim3(DD/128, M/128, SPLK), 256>>>(
            M, DD, DFFX, FFH, DFFX, W2H + (size_t)l*DFFX*DD, DD, PART, DD,
            nullptr, nullptr, nullptr, nullptr, nullptr);
        if (l == LTN - 1)
            ln_warp_k<2,0><<<M/8, 256>>>(XC, PART, l2s + l*DD, l2b + l*DD, out, nullptr, b2 + l*DD);
        else
            ln_warp_k<2,1><<<M/8, 256>>>(XC, PART, l2s + l*DD, l2b + l*DD, XC, XCH, b2 + l*DD);
    }
}